// round 1
// baseline (speedup 1.0000x reference)
#include <cuda_runtime.h>

// TriMip encoding: 3 planes, 8 mip levels (512 -> 4), 16 features, fp32.
// Strategy:
//   - Mip levels 1..7 are rebuilt each launch into a __device__ scratch
//     (allocation-free, deterministic, graph-capturable: kernels only).
//   - Level 0 is sampled directly from the input feature maps.
//   - Sampling: 12 threads per point (3 planes x 4 float4 feature quads).
//     Each thread: 2 mip levels x 4 bilinear texels = 8 float4 __ldg gathers,
//     one coalesced float4 store.

#define NLV 8

// Pyramid scratch for levels 1..7: sum_{l=1..7} 3 * (512>>l)^2 * 16 floats
//  = 4,194,048 floats (~16.8 MB)
__device__ float g_pyr[4194048];

// float offsets of each level inside g_pyr (level 0 unused -> fm directly)
__constant__ int c_off[8] = {0, 0, 3145728, 3932160, 4128768, 4177920, 4190208, 4193280};

// 2x2 box downsample: src level (size Ss=2*Sd) -> dst level (size Sd), 3 planes, 16 feats.
// src_off < 0 means read from fm, else read from g_pyr + src_off.
__global__ void mip_down(const float* __restrict__ fm, int src_off, int dst_off, int Sd) {
    int t = blockIdx.x * blockDim.x + threadIdx.x;
    int total = 3 * Sd * Sd * 4;      // one thread per output float4
    if (t >= total) return;
    int q   = t & 3;
    int idx = t >> 2;
    int xo  = idx % Sd; idx /= Sd;
    int yo  = idx % Sd;
    int pl  = idx / Sd;
    int Ss  = Sd * 2;

    const float4* src = (src_off < 0) ? (const float4*)fm
                                      : (const float4*)(g_pyr + src_off);
    const float4* s = src + pl * Ss * Ss * 4;
    const float4* r0 = s + ((2 * yo) * Ss + 2 * xo) * 4 + q;
    const float4* r1 = r0 + Ss * 4;
    float4 a = __ldg(r0);
    float4 b = __ldg(r0 + 4);
    float4 c = __ldg(r1);
    float4 d = __ldg(r1 + 4);
    float4 o;
    o.x = (a.x + b.x + c.x + d.x) * 0.25f;
    o.y = (a.y + b.y + c.y + d.y) * 0.25f;
    o.z = (a.z + b.z + c.z + d.z) * 0.25f;
    o.w = (a.w + b.w + c.w + d.w) * 0.25f;
    float4* dst = (float4*)(g_pyr + dst_off);
    dst[(pl * Sd * Sd + yo * Sd + xo) * 4 + q] = o;
}

__global__ void __launch_bounds__(256) trimip_sample(
    const float* __restrict__ x,
    const float* __restrict__ level,
    const float* __restrict__ fm,
    float* __restrict__ out,
    int N)
{
    int t = blockIdx.x * blockDim.x + threadIdx.x;
    if (t >= N * 12) return;
    int n = t / 12;
    int r = t - n * 12;
    int p = r >> 2;     // plane 0..2
    int q = r & 3;      // feature quad 0..3

    float xc0 = __ldg(&x[3 * n + 0]);
    float xc1 = __ldg(&x[3 * n + 1]);
    float xc2 = __ldg(&x[3 * n + 2]);
    // plane uv: p0 -> (x1, x2), p1 -> (x0, x2), p2 -> (x0, x1)
    float u = (p == 0) ? xc1 : xc0;   // maps to xx index (uv[...,0])
    float v = (p == 2) ? xc1 : xc2;   // maps to yy index (uv[...,1])

    float lvl = fminf(fmaxf(__ldg(&level[n]), 0.0f), (float)(NLV - 1));
    int   l0  = min((int)lvl, NLV - 2);
    float fr  = lvl - (float)l0;

    float4 acc = make_float4(0.f, 0.f, 0.f, 0.f);

    #pragma unroll
    for (int k = 0; k < 2; k++) {
        int   l = l0 + k;
        float w = k ? fr : (1.0f - fr);
        int   S = 512 >> l;

        const float4* base = (l == 0)
            ? ((const float4*)fm + p * 512 * 512 * 4)
            : ((const float4*)(g_pyr + c_off[l]) + p * S * S * 4);

        float px = u * (float)S - 0.5f;
        float py = v * (float)S - 0.5f;
        float fx = floorf(px);
        float fy = floorf(py);
        int ix0 = (int)fx;
        int iy0 = (int)fy;
        int ix1 = min(ix0 + 1, S - 1);
        int iy1 = min(iy0 + 1, S - 1);
        ix0 = max(ix0, 0);
        iy0 = max(iy0, 0);
        float ax = px - fx;
        float ay = py - fy;

        float4 v00 = __ldg(base + (iy0 * S + ix0) * 4 + q);
        float4 v10 = __ldg(base + (iy0 * S + ix1) * 4 + q);
        float4 v01 = __ldg(base + (iy1 * S + ix0) * 4 + q);
        float4 v11 = __ldg(base + (iy1 * S + ix1) * 4 + q);

        float w00 = w * (1.0f - ax) * (1.0f - ay);
        float w10 = w * ax * (1.0f - ay);
        float w01 = w * (1.0f - ax) * ay;
        float w11 = w * ax * ay;

        acc.x += w00 * v00.x + w10 * v10.x + w01 * v01.x + w11 * v11.x;
        acc.y += w00 * v00.y + w10 * v10.y + w01 * v01.y + w11 * v11.y;
        acc.z += w00 * v00.z + w10 * v10.z + w01 * v01.z + w11 * v11.z;
        acc.w += w00 * v00.w + w10 * v10.w + w01 * v01.w + w11 * v11.w;
    }

    // out[n][p*16 + q*4 .. +3]  (48 floats per point = 12 float4)
    ((float4*)out)[n * 12 + p * 4 + q] = acc;
}

extern "C" void kernel_launch(void* const* d_in, const int* in_sizes, int n_in,
                              void* d_out, int out_size) {
    const float* x     = (const float*)d_in[0];
    const float* level = (const float*)d_in[1];
    const float* fm    = (const float*)d_in[2];
    float* out = (float*)d_out;
    int N = in_sizes[0] / 3;

    static const int h_off[8] = {0, 0, 3145728, 3932160, 4128768, 4177920, 4190208, 4193280};

    // Build mip levels 1..7 (level l from level l-1)
    int src_off = -1;                 // level 0 = fm
    for (int l = 1; l < NLV; l++) {
        int Sd = 512 >> l;
        int total = 3 * Sd * Sd * 4;
        int blocks = (total + 255) / 256;
        mip_down<<<blocks, 256>>>(fm, src_off, h_off[l], Sd);
        src_off = h_off[l];
    }

    // Sample
    int total = N * 12;
    int blocks = (total + 255) / 256;
    trimip_sample<<<blocks, 256>>>(x, level, fm, out, N);
}

// round 2
// speedup vs baseline: 1.1863x; 1.1863x over previous
#include <cuda_runtime.h>
#include <cuda_fp16.h>

// TriMip encoding: 3 planes, 8 mip levels (512 -> 4), 16 features.
// v2: full pyramid (levels 0..7) stored as fp16 -> halves L2 gather traffic.
//   - fp32 build chain (mip_down) keeps quantization to a single rounding.
//   - Sampling: 6 threads per point (3 planes x 2 half-8 chunks).
//     Each thread: 2 levels x 4 texels = 8x 16B __ldg gathers, fp32 math,
//     two coalesced float4 stores.

#define NLV 8

// fp32 pyramid scratch, levels 1..7 (build chain): ~16.8 MB
__device__ float g_pyr[4194048];
// fp16 pyramid, levels 0..7: 3*16*sum(S_l^2) = 16,776,960 halves (~33.5 MB)
__device__ __half g_pyrh[16776960];

// float offsets of fp32 levels inside g_pyr (level 0 unused -> fm directly)
__constant__ int c_off[8]  = {0, 0, 3145728, 3932160, 4128768, 4177920, 4190208, 4193280};
// half offsets of fp16 levels inside g_pyrh
__constant__ int c_offh[8] = {0, 12582912, 15728640, 16515072, 16711680,
                              16760832, 16773120, 16776192};

// Convert level 0: fm (fp32) -> g_pyrh (fp16). One thread per 4 floats.
__global__ void conv_l0(const float* __restrict__ fm) {
    int t = blockIdx.x * blockDim.x + threadIdx.x;
    const int total = 3 * 512 * 512 * 4;   // float4 count
    if (t >= total) return;
    float4 v = __ldg((const float4*)fm + t);
    __half2 h0 = __floats2half2_rn(v.x, v.y);
    __half2 h1 = __floats2half2_rn(v.z, v.w);
    ((__half2*)g_pyrh)[t * 2 + 0] = h0;
    ((__half2*)g_pyrh)[t * 2 + 1] = h1;
}

// 2x2 box downsample in fp32; writes both fp32 (for next level) and fp16.
__global__ void mip_down(const float* __restrict__ fm, int src_off,
                         int dst_off, int dst_offh, int Sd) {
    int t = blockIdx.x * blockDim.x + threadIdx.x;
    int total = 3 * Sd * Sd * 4;      // one thread per output float4
    if (t >= total) return;
    int q   = t & 3;
    int idx = t >> 2;
    int xo  = idx % Sd; idx /= Sd;
    int yo  = idx % Sd;
    int pl  = idx / Sd;
    int Ss  = Sd * 2;

    const float4* src = (src_off < 0) ? (const float4*)fm
                                      : (const float4*)(g_pyr + src_off);
    const float4* s = src + pl * Ss * Ss * 4;
    const float4* r0 = s + ((2 * yo) * Ss + 2 * xo) * 4 + q;
    const float4* r1 = r0 + Ss * 4;
    float4 a = __ldg(r0);
    float4 b = __ldg(r0 + 4);
    float4 c = __ldg(r1);
    float4 d = __ldg(r1 + 4);
    float4 o;
    o.x = (a.x + b.x + c.x + d.x) * 0.25f;
    o.y = (a.y + b.y + c.y + d.y) * 0.25f;
    o.z = (a.z + b.z + c.z + d.z) * 0.25f;
    o.w = (a.w + b.w + c.w + d.w) * 0.25f;
    int eo = (pl * Sd * Sd + yo * Sd + xo) * 4 + q;
    ((float4*)(g_pyr + dst_off))[eo] = o;
    __half2 h0 = __floats2half2_rn(o.x, o.y);
    __half2 h1 = __floats2half2_rn(o.z, o.w);
    ((__half2*)(g_pyrh + dst_offh))[eo * 2 + 0] = h0;
    ((__half2*)(g_pyrh + dst_offh))[eo * 2 + 1] = h1;
}

__device__ __forceinline__ void fma_texel(float acc[8], float w, float4 raw) {
    const __half2* hp = (const __half2*)&raw;
    float2 f0 = __half22float2(hp[0]);
    float2 f1 = __half22float2(hp[1]);
    float2 f2 = __half22float2(hp[2]);
    float2 f3 = __half22float2(hp[3]);
    acc[0] = fmaf(w, f0.x, acc[0]);
    acc[1] = fmaf(w, f0.y, acc[1]);
    acc[2] = fmaf(w, f1.x, acc[2]);
    acc[3] = fmaf(w, f1.y, acc[3]);
    acc[4] = fmaf(w, f2.x, acc[4]);
    acc[5] = fmaf(w, f2.y, acc[5]);
    acc[6] = fmaf(w, f3.x, acc[6]);
    acc[7] = fmaf(w, f3.y, acc[7]);
}

__global__ void __launch_bounds__(256) trimip_sample(
    const float* __restrict__ x,
    const float* __restrict__ level,
    float* __restrict__ out,
    int N)
{
    int t = blockIdx.x * blockDim.x + threadIdx.x;
    if (t >= N * 6) return;
    int n = t / 6;
    int r = t - n * 6;
    int p = r >> 1;     // plane 0..2
    int h = r & 1;      // feature half-chunk (8 feats each)

    float xc0 = __ldg(&x[3 * n + 0]);
    float xc1 = __ldg(&x[3 * n + 1]);
    float xc2 = __ldg(&x[3 * n + 2]);
    // plane uv: p0 -> (x1, x2), p1 -> (x0, x2), p2 -> (x0, x1)
    float u = (p == 0) ? xc1 : xc0;   // xx index (uv[...,0])
    float v = (p == 2) ? xc1 : xc2;   // yy index (uv[...,1])

    float lvl = fminf(fmaxf(__ldg(&level[n]), 0.0f), (float)(NLV - 1));
    int   l0  = min((int)lvl, NLV - 2);
    float fr  = lvl - (float)l0;

    float acc[8] = {0.f, 0.f, 0.f, 0.f, 0.f, 0.f, 0.f, 0.f};

    #pragma unroll
    for (int k = 0; k < 2; k++) {
        int   l = l0 + k;
        float w = k ? fr : (1.0f - fr);
        int   S = 512 >> l;

        const __half* base = g_pyrh + c_offh[l] + (size_t)p * S * S * 16 + h * 8;

        float px = u * (float)S - 0.5f;
        float py = v * (float)S - 0.5f;
        float fx = floorf(px);
        float fy = floorf(py);
        int ix0 = (int)fx;
        int iy0 = (int)fy;
        int ix1 = min(ix0 + 1, S - 1);
        int iy1 = min(iy0 + 1, S - 1);
        ix0 = max(ix0, 0);
        iy0 = max(iy0, 0);
        float ax = px - fx;
        float ay = py - fy;

        float4 v00 = __ldg((const float4*)(base + (iy0 * S + ix0) * 16));
        float4 v10 = __ldg((const float4*)(base + (iy0 * S + ix1) * 16));
        float4 v01 = __ldg((const float4*)(base + (iy1 * S + ix0) * 16));
        float4 v11 = __ldg((const float4*)(base + (iy1 * S + ix1) * 16));

        float w00 = w * (1.0f - ax) * (1.0f - ay);
        float w10 = w * ax * (1.0f - ay);
        float w01 = w * (1.0f - ax) * ay;
        float w11 = w * ax * ay;

        fma_texel(acc, w00, v00);
        fma_texel(acc, w10, v10);
        fma_texel(acc, w01, v01);
        fma_texel(acc, w11, v11);
    }

    // out[n][p*16 + h*8 .. +7]  (48 floats per point)
    float4* o = (float4*)(out + (size_t)n * 48 + p * 16 + h * 8);
    o[0] = make_float4(acc[0], acc[1], acc[2], acc[3]);
    o[1] = make_float4(acc[4], acc[5], acc[6], acc[7]);
}

extern "C" void kernel_launch(void* const* d_in, const int* in_sizes, int n_in,
                              void* d_out, int out_size) {
    const float* x     = (const float*)d_in[0];
    const float* level = (const float*)d_in[1];
    const float* fm    = (const float*)d_in[2];
    float* out = (float*)d_out;
    int N = in_sizes[0] / 3;

    static const int h_off[8]  = {0, 0, 3145728, 3932160, 4128768,
                                  4177920, 4190208, 4193280};
    static const int h_offh[8] = {0, 12582912, 15728640, 16515072, 16711680,
                                  16760832, 16773120, 16776192};

    // Level 0 fp32 -> fp16
    {
        int total = 3 * 512 * 512 * 4;
        conv_l0<<<(total + 255) / 256, 256>>>(fm);
    }

    // Build mip levels 1..7 (fp32 chain, fp16 output)
    int src_off = -1;                 // level 0 = fm
    for (int l = 1; l < NLV; l++) {
        int Sd = 512 >> l;
        int total = 3 * Sd * Sd * 4;
        mip_down<<<(total + 255) / 256, 256>>>(fm, src_off, h_off[l], h_offh[l], Sd);
        src_off = h_off[l];
    }

    // Sample
    int total = N * 6;
    trimip_sample<<<(total + 255) / 256, 256>>>(x, level, out, N);
}